// round 3
// baseline (speedup 1.0000x reference)
#include <cuda_runtime.h>
#include <cstdint>

// TensorTrain fused kernel (round 1): tf32 mma.sync GEMM + fp32 scan, fully fused.
// BS=16384, N_CH=8, H=256, RANK=16, N_AGGR=4, T=64. Only cols 0..255 of the
// 272-wide ris are ever used (row 16 of the (17,16) reshape is dead).

#define TILE_B 64
#define HS 260   // sh_h / sh_ris row stride in floats (==4 mod 32 -> A-frag conflict-free)
#define US 264   // sh_u row stride in floats (==8 mod 32 -> B-frag conflict-free)

__device__ __forceinline__ float tf32r(float x) {
    unsigned u;
    asm("cvt.rna.tf32.f32 %0, %1;" : "=r"(u) : "f"(x));
    return __uint_as_float(u);
}

__device__ __forceinline__ void mma_tf32(float* d,
    unsigned a0, unsigned a1, unsigned a2, unsigned a3,
    unsigned b0, unsigned b1)
{
    asm volatile(
        "mma.sync.aligned.m16n8k8.row.col.f32.tf32.tf32.f32 "
        "{%0,%1,%2,%3}, {%4,%5,%6,%7}, {%8,%9}, {%0,%1,%2,%3};"
        : "+f"(d[0]), "+f"(d[1]), "+f"(d[2]), "+f"(d[3])
        : "r"(a0), "r"(a1), "r"(a2), "r"(a3), "r"(b0), "r"(b1));
}

extern "C" __global__ void __launch_bounds__(256, 1)
tt_fused_kernel(const float* __restrict__ NH,   // (16384, 8, 256)
                const float* __restrict__ TE,   // (16384, 64)
                const float* __restrict__ Umat, // (8, 4, 256, 272)
                const float* __restrict__ Bv,   // (8, 4, 1, 272)
                const float* __restrict__ UT,   // (4, 64, 16)
                const float* __restrict__ BT,   // (4, 1, 16)
                const float* __restrict__ UO,   // (4, 16, 256)
                const float* __restrict__ BO,   // (4, 1, 256)
                float* __restrict__ out)        // (16384, 1024)
{
    extern __shared__ float smem[];
    float* sh_h     = smem;                 // 64*HS = 16640 floats
    float* sh_u     = sh_h + 64 * HS;       // 32*US =  8448 floats
    float* sh_ris   = sh_u + 32 * US;       // 64*HS = 16640 floats
    float* sh_carry = sh_ris + 64 * HS;     // 64*4*16 = 4096 floats
    float* sh_bias  = sh_carry + 4096;      // 256 floats

    const int tid  = threadIdx.x;
    const int lane = tid & 31;
    const int warp = tid >> 5;
    const int wm   = warp & 3;   // M tile: rows wm*16 .. +15
    const int wn   = warp >> 2;  // N half: cols wn*128 .. +127
    const int gid  = lane >> 2;  // 0..7
    const int tig  = lane & 3;   // 0..3
    const int bbase = blockIdx.x * TILE_B;

    // ---------------- init: carry0 = TE_tile @ U_type + b_type (fp32) -------
    {
        // stage type tile (64x64) into sh_ris scratch, U_type (4096) into sh_u
        float* st  = sh_ris;
        float* sut = sh_u;
        #pragma unroll
        for (int j = 0; j < 4; j++) {
            int id = tid + j * 256;          // 1024 float4
            int s  = id >> 4, c4 = id & 15;
            float4 v = __ldg((const float4*)(TE + (size_t)(bbase + s) * 64 + c4 * 4));
            *(float4*)(st + s * 64 + c4 * 4) = v;
        }
        #pragma unroll
        for (int j = 0; j < 4; j++) {
            int id = tid + j * 256;          // 1024 float4
            float4 v = __ldg(((const float4*)UT) + id);
            *(float4*)(sut + id * 4) = v;
        }
        __syncthreads();
        #pragma unroll
        for (int j = 0; j < 16; j++) {
            int item = tid + j * 256;        // 4096 items
            int s = item >> 6;
            int a = (item >> 4) & 3;
            int q = item & 15;
            float v = __ldg(BT + a * 16 + q);
            const float* srow = st + s * 64;
            const float* ut   = sut + a * 64 * 16 + q;
            #pragma unroll 8
            for (int t = 0; t < 64; t++) v += srow[t] * ut[t * 16];
            sh_carry[(s * 4 + a) * 16 + q] = v;
        }
        __syncthreads();
    }

    // ---------------- main loop: channels x aggregators --------------------
    for (int c = 0; c < 8; c++) {
        // stage h tile (64 x 256) as tf32 into sh_h
        #pragma unroll
        for (int j = 0; j < 16; j++) {
            int id = tid + j * 256;          // 4096 float4
            int s  = id >> 6, c4 = id & 63;
            float4 v = __ldg((const float4*)(NH + ((size_t)(bbase + s) * 8 + c) * 256 + c4 * 4));
            float4 w = make_float4(tf32r(v.x), tf32r(v.y), tf32r(v.z), tf32r(v.w));
            *(float4*)(sh_h + s * HS + c4 * 4) = w;
        }
        // (sync happens inside first k-chunk below before sh_h is read)

        for (int a = 0; a < 4; a++) {
            // stage bias (cols 0..255)
            sh_bias[tid] = __ldg(Bv + (size_t)(c * 4 + a) * 272 + tid);

            float acc[64];
            #pragma unroll
            for (int i = 0; i < 64; i++) acc[i] = 0.f;

            const float* ubase = Umat + (size_t)((c * 4 + a) * 256) * 272;

            for (int kc = 0; kc < 8; kc++) {
                // stage U chunk: rows kc*32..+31, cols 0..255, tf32
                #pragma unroll
                for (int j = 0; j < 8; j++) {
                    int id = tid + j * 256;  // 2048 float4
                    int r  = id >> 6, c4 = id & 63;
                    float4 v = __ldg((const float4*)(ubase + (size_t)(kc * 32 + r) * 272 + c4 * 4));
                    float4 w = make_float4(tf32r(v.x), tf32r(v.y), tf32r(v.z), tf32r(v.w));
                    *(float4*)(sh_u + r * US + c4 * 4) = w;
                }
                __syncthreads();

                #pragma unroll
                for (int ks = 0; ks < 4; ks++) {
                    const int krow = kc * 32 + ks * 8;
                    unsigned a0 = __float_as_uint(sh_h[(wm * 16 + gid) * HS + krow + tig]);
                    unsigned a1 = __float_as_uint(sh_h[(wm * 16 + gid + 8) * HS + krow + tig]);
                    unsigned a2 = __float_as_uint(sh_h[(wm * 16 + gid) * HS + krow + tig + 4]);
                    unsigned a3 = __float_as_uint(sh_h[(wm * 16 + gid + 8) * HS + krow + tig + 4]);
                    #pragma unroll
                    for (int nt = 0; nt < 16; nt++) {
                        int ncol = wn * 128 + nt * 8 + gid;
                        unsigned b0 = __float_as_uint(sh_u[(ks * 8 + tig) * US + ncol]);
                        unsigned b1 = __float_as_uint(sh_u[(ks * 8 + tig + 4) * US + ncol]);
                        mma_tf32(&acc[nt * 4], a0, a1, a2, a3, b0, b1);
                    }
                }
                __syncthreads();
            }

            // store acc + bias -> sh_ris
            #pragma unroll
            for (int nt = 0; nt < 16; nt++) {
                int col = wn * 128 + nt * 8 + tig * 2;
                int row = wm * 16 + gid;
                sh_ris[row * HS + col]           = acc[nt * 4 + 0] + sh_bias[col];
                sh_ris[row * HS + col + 1]       = acc[nt * 4 + 1] + sh_bias[col + 1];
                sh_ris[(row + 8) * HS + col]     = acc[nt * 4 + 2] + sh_bias[col];
                sh_ris[(row + 8) * HS + col + 1] = acc[nt * 4 + 3] + sh_bias[col + 1];
            }
            __syncthreads();

            // scan update: new[q] = ris[240+q] + sum_r carry[r] * ris[r*16+q]
            float nv[4];
            #pragma unroll
            for (int j = 0; j < 4; j++) {
                int item = tid + j * 256;    // 1024 items (64 s x 16 q)
                int s = item >> 4, q = item & 15;
                const float* rr = sh_ris + s * HS;
                const float* cy = sh_carry + (s * 4 + a) * 16;
                float v = rr[240 + q];
                #pragma unroll
                for (int r = 0; r < 16; r++) v += cy[r] * rr[r * 16 + q];
                nv[j] = v;
            }
            __syncthreads();
            #pragma unroll
            for (int j = 0; j < 4; j++) {
                int item = tid + j * 256;
                int s = item >> 4, q = item & 15;
                sh_carry[(s * 4 + a) * 16 + q] = nv[j];
            }
            __syncthreads();
        }
    }

    // ---------------- epilogue: out = carry @ U_output + b_output (fp32) ----
    {
        float* suo = sh_h;  // reuse: 4*16*256 = 16384 floats
        #pragma unroll
        for (int j = 0; j < 16; j++) {
            int id = tid + j * 256;          // 4096 float4
            float4 v = __ldg(((const float4*)UO) + id);
            *(float4*)(suo + id * 4) = v;
        }
        __syncthreads();

        #pragma unroll
        for (int kk = 0; kk < 4; kk++) {     // kk == aggregator a, hh == tid
            float bov = __ldg(BO + kk * 256 + tid);
            const float* uo = suo + kk * 16 * 256 + tid;
            for (int s = 0; s < 64; s++) {
                const float* cy = sh_carry + (s * 4 + kk) * 16;
                float v = bov;
                #pragma unroll
                for (int q = 0; q < 16; q++) v += cy[q] * uo[q * 256];
                out[(size_t)(bbase + s) * 1024 + kk * 256 + tid] = v;
            }
        }
    }
}

extern "C" void kernel_launch(void* const* d_in, const int* in_sizes, int n_in,
                              void* d_out, int out_size)
{
    const float* NH = (const float*)d_in[0];
    const float* TE = (const float*)d_in[1];
    const float* U  = (const float*)d_in[2];
    const float* Bv = (const float*)d_in[3];
    const float* UT = (const float*)d_in[4];
    const float* BT = (const float*)d_in[5];
    const float* UO = (const float*)d_in[6];
    const float* BO = (const float*)d_in[7];
    float* out = (float*)d_out;

    const int smem_bytes = (64 * HS + 32 * US + 64 * HS + 4096 + 256) * 4;
    cudaFuncSetAttribute(tt_fused_kernel,
                         cudaFuncAttributeMaxDynamicSharedMemorySize, smem_bytes);

    tt_fused_kernel<<<16384 / TILE_B, 256, smem_bytes>>>(
        NH, TE, U, Bv, UT, BT, UO, BO, out);
}